// round 1
// baseline (speedup 1.0000x reference)
#include <cuda_runtime.h>
#include <math.h>

// Problem constants
#define BSZ   4096
#define HDIM  300
#define TT    43
#define NCLS  80
#define NB    16     // batch rows per CTA
#define NBP   8      // float2 batch pairs
#define BT    608    // threads per block (19 full warps; 600 active owners)

// ---------------- device scratch (allocation-free rule: __device__ globals) ---
__device__ float  g_xT[(size_t)TT * HDIM * BSZ];        // [t][h][b]  211 MB
__device__ float  g_hs[(size_t)BSZ * TT * HDIM];        // [b][t][h]  211 MB
__device__ float4 g_W4[2 * 600 * 300];                  // [d][k(600)][u(300)] -> (i,f,g,o)
__device__ float  g_bias[2 * 1200];                     // b_ih + b_hh

// ---------------- helpers ----------------------------------------------------
__device__ __forceinline__ float2 ffma2(float2 a, float2 b, float2 c) {
    unsigned long long au = *reinterpret_cast<unsigned long long*>(&a);
    unsigned long long bu = *reinterpret_cast<unsigned long long*>(&b);
    unsigned long long cu = *reinterpret_cast<unsigned long long*>(&c);
    unsigned long long du;
    asm("fma.rn.f32x2 %0, %1, %2, %3;" : "=l"(du) : "l"(au), "l"(bu), "l"(cu));
    return *reinterpret_cast<float2*>(&du);
}

__device__ __forceinline__ float fsig(float x) {
    // 1/(1+e^-x); safe at extremes (exp->0 or inf -> rcp(inf)=0)
    return __fdividef(1.0f, 1.0f + __expf(-x));
}
__device__ __forceinline__ float ftanh_(float x) {
    // 1 - 2/(e^{2x}+1); e=inf -> 1, e=0 -> -1
    float e = __expf(2.0f * x);
    return 1.0f - __fdividef(2.0f, e + 1.0f);
}

// ---------------- prep kernels -----------------------------------------------
// x[B][H][T] -> g_xT[t][h][b]
__global__ void transpose_x_kernel(const float* __restrict__ x) {
    __shared__ float tile[32][43];
    int b0 = blockIdx.x * 32;
    int h  = blockIdx.y;
    for (int j = threadIdx.x; j < 32 * TT; j += blockDim.x) {
        int i = j / TT, t = j - i * TT;
        tile[i][t] = x[((size_t)(b0 + i) * HDIM + h) * TT + t];
    }
    __syncthreads();
    for (int j = threadIdx.x; j < TT * 32; j += blockDim.x) {
        int t = j >> 5, i = j & 31;
        g_xT[((size_t)t * HDIM + h) * BSZ + b0 + i] = tile[i][t];
    }
}

// Build gate-interleaved combined weights: g_W4[(d*600+k)*300+u] = (i,f,g,o)
// k<300 -> w_ih[d][gate*300+u][k] ; k>=300 -> w_hh[d][gate*300+u][k-300]
__global__ void prep_w_kernel(const float* __restrict__ wih, const float* __restrict__ whh) {
    int idx = blockIdx.x * blockDim.x + threadIdx.x;   // over 2*600*300*4
    if (idx >= 2 * 600 * 300 * 4) return;
    int gate = idx & 3;
    int rest = idx >> 2;
    int u = rest % 300;
    int k = (rest / 300) % 600;
    int d = rest / (300 * 600);
    int col = gate * 300 + u;
    float v;
    if (k < 300) v = wih[((size_t)d * 1200 + col) * 300 + k];
    else         v = whh[((size_t)d * 1200 + col) * 300 + (k - 300)];
    ((float*)g_W4)[idx] = v;
}

__global__ void prep_b_kernel(const float* __restrict__ bih, const float* __restrict__ bhh) {
    int idx = blockIdx.x * blockDim.x + threadIdx.x;
    if (idx < 2400) g_bias[idx] = bih[idx] + bhh[idx];
}

// ---------------- fused LSTM + attention + FC kernel --------------------------
// Dynamic smem layout (bytes):
//   [0      , 19200 )  x_sh  : float2[300][8]      (overlaid by hstar[16][300] in epilogue)
//   [19200  , 57600 )  h_sh  : float2[8][600]      (col = d*300+u)
//   [57600  , 96000 )  c_sh  : float [16][600]
//   [19200  , 115200)  fcT   : float [300][80]     (epilogue overlay of h_sh+c_sh+pad)
//   [115200 , 120000)  aux   : cw[300], e[16][44], l[80], p[80]
#define SMEM_BYTES 120000

__global__ __launch_bounds__(BT, 1)
void lstm_attn_kernel(const float* __restrict__ conv_w,
                      const float* __restrict__ fc_w,
                      const float* __restrict__ fc_b,
                      float* __restrict__ out) {
    extern __shared__ char smem_raw[];
    float2* x_sh  = (float2*)(smem_raw);
    float2* h_sh  = (float2*)(smem_raw + 19200);
    float*  c_sh  = (float*) (smem_raw + 57600);
    float*  fcT   = (float*) (smem_raw + 19200);
    float*  aux   = (float*) (smem_raw + 115200);
    float*  cw_sh = aux;                 // 300
    float*  e_sh  = aux + 300;           // [16][44]
    float*  l_sh  = aux + 300 + 16 * 44; // [80]
    float*  p_sh  = l_sh + 80;           // [80]
    float*  hstar = (float*)(smem_raw);  // overlays x_sh: [16][300]

    const int tid = threadIdx.x;
    const int b0  = blockIdx.x * NB;

    // zero states
    for (int i = tid; i < 8 * 600; i += BT) h_sh[i] = make_float2(0.f, 0.f);
    for (int i = tid; i < 16 * 600; i += BT) c_sh[i] = 0.f;

    const bool active = (tid < 600);
    const int d = active ? (tid / 300) : 0;
    const int u = active ? (tid - d * 300) : 0;

    float bi_ = 0.f, bf_ = 0.f, bg_ = 0.f, bo_ = 0.f;
    const float4* W4 = g_W4 + (size_t)d * 600 * 300 + u;
    if (active) {
        const float* bb = g_bias + d * 1200;
        bi_ = bb[u]; bf_ = bb[300 + u]; bg_ = bb[600 + u]; bo_ = bb[900 + u];
    }
    __syncthreads();

    // ---------------- time loop ----------------
    for (int t = 0; t < TT; t++) {
        // stage x_t for our batch rows: g_xT[t][k][b0..b0+15] -> x_sh[k][bp]
        const float* xsrc = g_xT + (size_t)t * HDIM * BSZ + b0;
        for (int i = tid; i < 300 * NBP; i += BT) {
            int k = i >> 3, bp = i & 7;
            x_sh[i] = *(const float2*)(xsrc + (size_t)k * BSZ + 2 * bp);
        }
        __syncthreads();

        float2 ai[NBP], af[NBP], ag[NBP], ao[NBP];
        if (active) {
            #pragma unroll
            for (int bp = 0; bp < NBP; bp++) {
                ai[bp] = make_float2(bi_, bi_); af[bp] = make_float2(bf_, bf_);
                ag[bp] = make_float2(bg_, bg_); ao[bp] = make_float2(bo_, bo_);
            }
            // x contribution (k = 0..299)
            #pragma unroll 2
            for (int k = 0; k < 300; k++) {
                float4 w = W4[(size_t)k * 300];
                float2 v[NBP];
                #pragma unroll
                for (int bp = 0; bp < NBP; bp++) v[bp] = x_sh[k * NBP + bp];
                float2 wp;
                wp = make_float2(w.x, w.x);
                #pragma unroll
                for (int bp = 0; bp < NBP; bp++) ai[bp] = ffma2(v[bp], wp, ai[bp]);
                wp = make_float2(w.y, w.y);
                #pragma unroll
                for (int bp = 0; bp < NBP; bp++) af[bp] = ffma2(v[bp], wp, af[bp]);
                wp = make_float2(w.z, w.z);
                #pragma unroll
                for (int bp = 0; bp < NBP; bp++) ag[bp] = ffma2(v[bp], wp, ag[bp]);
                wp = make_float2(w.w, w.w);
                #pragma unroll
                for (int bp = 0; bp < NBP; bp++) ao[bp] = ffma2(v[bp], wp, ao[bp]);
            }
            // h contribution (k = 300..599), h_sh[bp][d*300+k]
            #pragma unroll 2
            for (int k = 0; k < 300; k++) {
                float4 w = W4[(size_t)(300 + k) * 300];
                float2 v[NBP];
                #pragma unroll
                for (int bp = 0; bp < NBP; bp++) v[bp] = h_sh[bp * 600 + d * 300 + k];
                float2 wp;
                wp = make_float2(w.x, w.x);
                #pragma unroll
                for (int bp = 0; bp < NBP; bp++) ai[bp] = ffma2(v[bp], wp, ai[bp]);
                wp = make_float2(w.y, w.y);
                #pragma unroll
                for (int bp = 0; bp < NBP; bp++) af[bp] = ffma2(v[bp], wp, af[bp]);
                wp = make_float2(w.z, w.z);
                #pragma unroll
                for (int bp = 0; bp < NBP; bp++) ag[bp] = ffma2(v[bp], wp, ag[bp]);
                wp = make_float2(w.w, w.w);
                #pragma unroll
                for (int bp = 0; bp < NBP; bp++) ao[bp] = ffma2(v[bp], wp, ao[bp]);
            }
        }
        __syncthreads();

        // gate nonlinearities + state update; h_sh[bp][tid] (tid == d*300+u)
        if (active) {
            #pragma unroll
            for (int bp = 0; bp < NBP; bp++) {
                float2 hv;
                {
                    float ii = fsig(ai[bp].x), ff = fsig(af[bp].x);
                    float gg = ftanh_(ag[bp].x), oo = fsig(ao[bp].x);
                    float c  = c_sh[(2 * bp) * 600 + tid];
                    c = ff * c + ii * gg;
                    c_sh[(2 * bp) * 600 + tid] = c;
                    hv.x = oo * ftanh_(c);
                }
                {
                    float ii = fsig(ai[bp].y), ff = fsig(af[bp].y);
                    float gg = ftanh_(ag[bp].y), oo = fsig(ao[bp].y);
                    float c  = c_sh[(2 * bp + 1) * 600 + tid];
                    c = ff * c + ii * gg;
                    c_sh[(2 * bp + 1) * 600 + tid] = c;
                    hv.y = oo * ftanh_(c);
                }
                h_sh[bp * 600 + tid] = hv;
            }
        }
        __syncthreads();

        // hsum = h[dir0] + h[dir1] -> g_hs[b][t][u]
        for (int i = tid; i < NB * 300; i += BT) {
            int b = i / 300, uu = i - b * 300;
            float2 h0 = h_sh[(b >> 1) * 600 + uu];
            float2 h1 = h_sh[(b >> 1) * 600 + 300 + uu];
            float s = (b & 1) ? (h0.y + h1.y) : (h0.x + h1.x);
            g_hs[((size_t)(b0 + b) * TT + t) * 300 + uu] = s;
        }
        // next iteration's x_sh store is fenced by the first __syncthreads in the loop
    }
    __syncthreads();

    // ---------------- attention epilogue ----------------
    // stage conv_w and transposed fc weights
    for (int i = tid; i < 300; i += BT) cw_sh[i] = conv_w[i];
    for (int i = tid; i < 300 * NCLS; i += BT) {
        int uu = i / NCLS, cls = i - uu * NCLS;
        fcT[i] = fc_w[(size_t)cls * 300 + uu];
    }
    __syncthreads();

    // Phase A: e[b][t] = sum_u tanh(hs[b][t][u]) * conv_w[u]   (one warp per task)
    {
        int wid = tid >> 5, lane = tid & 31;
        for (int task = wid; task < NB * TT; task += (BT / 32)) {
            int b = task / TT, t = task - b * TT;
            const float* hp = g_hs + ((size_t)(b0 + b) * TT + t) * 300;
            float s = 0.f;
            for (int uu = lane; uu < 300; uu += 32) s += ftanh_(hp[uu]) * cw_sh[uu];
            #pragma unroll
            for (int o = 16; o > 0; o >>= 1) s += __shfl_xor_sync(0xffffffffu, s, o);
            if (lane == 0) e_sh[b * 44 + t] = s;
        }
    }
    __syncthreads();

    // softmax over time per batch row
    if (tid < NB) {
        float m = -1e30f;
        for (int t = 0; t < TT; t++) m = fmaxf(m, e_sh[tid * 44 + t]);
        float ss = 0.f;
        for (int t = 0; t < TT; t++) { float p = __expf(e_sh[tid * 44 + t] - m); e_sh[tid * 44 + t] = p; ss += p; }
        float inv = 1.0f / ss;
        for (int t = 0; t < TT; t++) e_sh[tid * 44 + t] *= inv;
    }
    __syncthreads();

    // Phase B: r[b][u] = sum_t hs[b][t][u] * alpha[b][t]; hstar = tanh(r)
    for (int i = tid; i < NB * 300; i += BT) {
        int b = i / 300, uu = i - b * 300;
        const float* hp = g_hs + (size_t)(b0 + b) * TT * 300 + uu;
        float acc = 0.f;
        for (int t = 0; t < TT; t++) acc += hp[(size_t)t * 300] * e_sh[b * 44 + t];
        hstar[i] = ftanh_(acc);
    }
    __syncthreads();

    // FC + class softmax
    for (int b = 0; b < NB; b++) {
        if (tid < NCLS) {
            float acc = fc_b[tid];
            const float* hv = hstar + b * 300;
            for (int uu = 0; uu < 300; uu++) acc += hv[uu] * fcT[uu * NCLS + tid];
            l_sh[tid] = acc;
        }
        __syncthreads();
        if (tid < NCLS) {
            float m = -1e30f;
            for (int j = 0; j < NCLS; j++) m = fmaxf(m, l_sh[j]);
            p_sh[tid] = __expf(l_sh[tid] - m);
        }
        __syncthreads();
        if (tid < NCLS) {
            float s = 0.f;
            for (int j = 0; j < NCLS; j++) s += p_sh[j];
            out[(size_t)(b0 + b) * NCLS + tid] = p_sh[tid] / s;
        }
        __syncthreads();
    }
}

// ---------------- launch ------------------------------------------------------
extern "C" void kernel_launch(void* const* d_in, const int* in_sizes, int n_in,
                              void* d_out, int out_size) {
    const float* x      = (const float*)d_in[0];
    const float* w_ih   = (const float*)d_in[1];
    const float* w_hh   = (const float*)d_in[2];
    const float* b_ih   = (const float*)d_in[3];
    const float* b_hh   = (const float*)d_in[4];
    const float* conv_w = (const float*)d_in[5];
    const float* fc_w   = (const float*)d_in[6];
    const float* fc_b   = (const float*)d_in[7];
    float* out = (float*)d_out;

    cudaFuncSetAttribute(lstm_attn_kernel,
                         cudaFuncAttributeMaxDynamicSharedMemorySize, SMEM_BYTES);

    transpose_x_kernel<<<dim3(BSZ / 32, HDIM), 256>>>(x);
    prep_w_kernel<<<(2 * 600 * 300 * 4 + 255) / 256, 256>>>(w_ih, w_hh);
    prep_b_kernel<<<(2400 + 255) / 256, 256>>>(b_ih, b_hh);
    lstm_attn_kernel<<<BSZ / NB, BT, SMEM_BYTES>>>(conv_w, fc_w, fc_b, out);
}

// round 3
// speedup vs baseline: 1.8501x; 1.8501x over previous
#include <cuda_runtime.h>
#include <math.h>

// Problem constants
#define BSZ   4096
#define HDIM  300
#define TT    43
#define NCLS  80
#define NB    16     // batch rows per CTA
#define NBP   8      // float2 batch pairs
#define BT    608    // threads per block (19 warps; 600 active owners)
#define HS    10     // h_sh row stride in float2 (80B, 16B-aligned, conflict-padded)

// ---------------- device scratch (allocation-free rule: __device__ globals) ---
__device__ float  g_xT[(size_t)TT * HDIM * BSZ];          // [t][h][b]
__device__ float  g_hs[(size_t)BSZ * TT * HDIM];          // [b][t][h]
__device__ float4 g_W4[2 * 600 * 300 + 600];              // [d][k(600)][u(300)] -> (i,f,g,o), +pad
__device__ float  g_bias[2 * 1200];                       // b_ih + b_hh
__device__ float  g_zx[(size_t)TT * 2 * 4 * BSZ * HDIM];  // [t][d][g][b][u]  x-part + bias

// ---------------- helpers ----------------------------------------------------
__device__ __forceinline__ float2 ffma2(float2 a, float2 b, float2 c) {
    unsigned long long au = *reinterpret_cast<unsigned long long*>(&a);
    unsigned long long bu = *reinterpret_cast<unsigned long long*>(&b);
    unsigned long long cu = *reinterpret_cast<unsigned long long*>(&c);
    unsigned long long du;
    asm("fma.rn.f32x2 %0, %1, %2, %3;" : "=l"(du) : "l"(au), "l"(bu), "l"(cu));
    return *reinterpret_cast<float2*>(&du);
}
__device__ __forceinline__ float fsig(float x) {
    return __fdividef(1.0f, 1.0f + __expf(-x));
}
__device__ __forceinline__ float ftanh_(float x) {
    float e = __expf(2.0f * x);
    return 1.0f - __fdividef(2.0f, e + 1.0f);
}

// ---------------- prep kernels -----------------------------------------------
__global__ void transpose_x_kernel(const float* __restrict__ x) {
    __shared__ float tile[32][43];
    int b0 = blockIdx.x * 32;
    int h  = blockIdx.y;
    for (int j = threadIdx.x; j < 32 * TT; j += blockDim.x) {
        int i = j / TT, t = j - i * TT;
        tile[i][t] = x[((size_t)(b0 + i) * HDIM + h) * TT + t];
    }
    __syncthreads();
    for (int j = threadIdx.x; j < TT * 32; j += blockDim.x) {
        int t = j >> 5, i = j & 31;
        g_xT[((size_t)t * HDIM + h) * BSZ + b0 + i] = tile[i][t];
    }
}

// g_W4[(d*600+k)*300+u] = (i,f,g,o); k<300 from w_ih, k>=300 from w_hh
__global__ void prep_w_kernel(const float* __restrict__ wih, const float* __restrict__ whh) {
    int idx = blockIdx.x * blockDim.x + threadIdx.x;
    if (idx >= 2 * 600 * 300 * 4) return;
    int gate = idx & 3;
    int rest = idx >> 2;
    int u = rest % 300;
    int k = (rest / 300) % 600;
    int d = rest / (300 * 600);
    int col = gate * 300 + u;
    float v;
    if (k < 300) v = wih[((size_t)d * 1200 + col) * 300 + k];
    else         v = whh[((size_t)d * 1200 + col) * 300 + (k - 300)];
    ((float*)g_W4)[idx] = v;
}

__global__ void prep_b_kernel(const float* __restrict__ bih, const float* __restrict__ bhh) {
    int idx = blockIdx.x * blockDim.x + threadIdx.x;
    if (idx < 2400) g_bias[idx] = bih[idx] + bhh[idx];
}

// ---------------- shared FMA block macro --------------------------------------
#define GATE_FMAS(WA, V)                                                        \
    {                                                                           \
        float2 wp;                                                              \
        wp = make_float2((WA).x, (WA).x);                                       \
        _Pragma("unroll")                                                       \
        for (int bp = 0; bp < NBP; bp++) ai[bp] = ffma2((V)[bp], wp, ai[bp]);   \
        wp = make_float2((WA).y, (WA).y);                                       \
        _Pragma("unroll")                                                       \
        for (int bp = 0; bp < NBP; bp++) af[bp] = ffma2((V)[bp], wp, af[bp]);   \
        wp = make_float2((WA).z, (WA).z);                                       \
        _Pragma("unroll")                                                       \
        for (int bp = 0; bp < NBP; bp++) ag[bp] = ffma2((V)[bp], wp, ag[bp]);   \
        wp = make_float2((WA).w, (WA).w);                                       \
        _Pragma("unroll")                                                       \
        for (int bp = 0; bp < NBP; bp++) ao[bp] = ffma2((V)[bp], wp, ao[bp]);   \
    }

// ---------------- precompute: Zx[t][d][g][b][u] = x_t @ W_ih^T + bias ---------
__global__ __launch_bounds__(BT, 1)
void precompute_zx_kernel() {
    __shared__ float2 x_sh[300 * NBP];   // 19.2 KB
    const int tid = threadIdx.x;
    const int b0  = blockIdx.x * NB;
    const int t   = blockIdx.y;

    // stage x_t for our batch rows (coalesced from g_xT[t][k][b])
    const float* xsrc = g_xT + (size_t)t * HDIM * BSZ + b0;
    for (int i = tid; i < 300 * NBP; i += BT) {
        int k = i >> 3, bp = i & 7;
        x_sh[i] = *(const float2*)(xsrc + (size_t)k * BSZ + 2 * bp);
    }
    __syncthreads();

    if (tid >= 600) return;
    const int d = tid / 300;
    const int u = tid - d * 300;

    float2 ai[NBP], af[NBP], ag[NBP], ao[NBP];
    {
        const float* bb = g_bias + d * 1200;
        float bi_ = bb[u], bf_ = bb[300 + u], bg_ = bb[600 + u], bo_ = bb[900 + u];
        #pragma unroll
        for (int bp = 0; bp < NBP; bp++) {
            ai[bp] = make_float2(bi_, bi_); af[bp] = make_float2(bf_, bf_);
            ag[bp] = make_float2(bg_, bg_); ao[bp] = make_float2(bo_, bo_);
        }
    }

    const float4* Wk = g_W4 + (size_t)d * 600 * 300 + u;   // k = 0..299 slice
    float4 w0 = Wk[0];
    float4 w1 = Wk[300];
    for (int k = 0; k < 300; k++) {
        float4 wa = w0;
        w0 = w1;
        w1 = Wk[(size_t)(k + 2) * 300];   // tail reads run into W_hh region: valid, unused
        const float4* vp = (const float4*)(x_sh + k * NBP);
        float4 p0 = vp[0], p1 = vp[1], p2 = vp[2], p3 = vp[3];
        float2 v[NBP] = { make_float2(p0.x, p0.y), make_float2(p0.z, p0.w),
                          make_float2(p1.x, p1.y), make_float2(p1.z, p1.w),
                          make_float2(p2.x, p2.y), make_float2(p2.z, p2.w),
                          make_float2(p3.x, p3.y), make_float2(p3.z, p3.w) };
        GATE_FMAS(wa, v);
    }

    // store: g_zx[((t*2+d)*4+g)*BSZ*300 + (b0+b)*300 + u], lanes coalesced over u
    const size_t GS = (size_t)BSZ * 300;
    float* zo = g_zx + (((size_t)t * 2 + d) * 4) * GS + (size_t)b0 * 300 + u;
    #pragma unroll
    for (int bp = 0; bp < NBP; bp++) {
        zo[0 * GS + (2 * bp) * 300]     = ai[bp].x;  zo[0 * GS + (2 * bp + 1) * 300] = ai[bp].y;
        zo[1 * GS + (2 * bp) * 300]     = af[bp].x;  zo[1 * GS + (2 * bp + 1) * 300] = af[bp].y;
        zo[2 * GS + (2 * bp) * 300]     = ag[bp].x;  zo[2 * GS + (2 * bp + 1) * 300] = ag[bp].y;
        zo[3 * GS + (2 * bp) * 300]     = ao[bp].x;  zo[3 * GS + (2 * bp + 1) * 300] = ao[bp].y;
    }
}

// ---------------- recurrent kernel + attention epilogue -----------------------
// smem (dynamic, 120000 B):
//   recurrence:  h_sh  float2[600][HS]  at 0      (48000 B)
//                c_sh  float [16][608]  at 48000  (38912 B)
//   epilogue:    hstar float [16][300]  at 0
//                fcT   float [300][80]  at 19200
//                aux                    at 115200 (cw[300], e[16][44], l[80], p[80])
#define SMEM_BYTES 120000

__global__ __launch_bounds__(BT, 1)
void lstm_rec_kernel(const float* __restrict__ conv_w,
                     const float* __restrict__ fc_w,
                     const float* __restrict__ fc_b,
                     float* __restrict__ out) {
    extern __shared__ char smem_raw[];
    float2* h_sh  = (float2*)(smem_raw);
    float*  c_sh  = (float*) (smem_raw + 48000);
    float*  hstar = (float*) (smem_raw);
    float*  fcT   = (float*) (smem_raw + 19200);
    float*  aux   = (float*) (smem_raw + 115200);
    float*  cw_sh = aux;
    float*  e_sh  = aux + 300;
    float*  l_sh  = aux + 300 + 16 * 44;
    float*  p_sh  = l_sh + 80;

    const int tid = threadIdx.x;
    const int b0  = blockIdx.x * NB;

    for (int i = tid; i < 600 * HS; i += BT) h_sh[i] = make_float2(0.f, 0.f);
    for (int i = tid; i < 16 * 608; i += BT) c_sh[i] = 0.f;

    const bool active = (tid < 600);
    const int d = active ? (tid / 300) : 0;
    const int u = active ? (tid - d * 300) : 0;
    const float4* Wk = g_W4 + ((size_t)d * 600 + 300) * 300 + u;  // W_hh slice
    const size_t GS = (size_t)BSZ * 300;
    __syncthreads();

    for (int t = 0; t < TT; t++) {
        float2 ai[NBP], af[NBP], ag[NBP], ao[NBP];
        if (active) {
            // init accumulators from precomputed x-part (+bias)
            const float* zp = g_zx + (((size_t)t * 2 + d) * 4) * GS + (size_t)b0 * 300 + u;
            #pragma unroll
            for (int bp = 0; bp < NBP; bp++) {
                ai[bp].x = zp[0 * GS + (2 * bp) * 300]; ai[bp].y = zp[0 * GS + (2 * bp + 1) * 300];
                af[bp].x = zp[1 * GS + (2 * bp) * 300]; af[bp].y = zp[1 * GS + (2 * bp + 1) * 300];
                ag[bp].x = zp[2 * GS + (2 * bp) * 300]; ag[bp].y = zp[2 * GS + (2 * bp + 1) * 300];
                ao[bp].x = zp[3 * GS + (2 * bp) * 300]; ao[bp].y = zp[3 * GS + (2 * bp + 1) * 300];
            }
            // recurrent GEMM: z += h_{t-1} @ W_hh^T
            const float2* hb = h_sh + (size_t)d * 300 * HS;
            float4 w0 = Wk[0];
            float4 w1 = Wk[300];
            for (int k = 0; k < 300; k++) {
                float4 wa = w0;
                w0 = w1;
                w1 = Wk[(size_t)(k + 2) * 300];   // tail reads hit pad region: valid, unused
                const float4* vp = (const float4*)(hb + (size_t)k * HS);
                float4 p0 = vp[0], p1 = vp[1], p2 = vp[2], p3 = vp[3];
                float2 v[NBP] = { make_float2(p0.x, p0.y), make_float2(p0.z, p0.w),
                                  make_float2(p1.x, p1.y), make_float2(p1.z, p1.w),
                                  make_float2(p2.x, p2.y), make_float2(p2.z, p2.w),
                                  make_float2(p3.x, p3.y), make_float2(p3.z, p3.w) };
                GATE_FMAS(wa, v);
            }
        }
        __syncthreads();   // all reads of h_{t-1} complete

        if (active) {
            #pragma unroll
            for (int bp = 0; bp < NBP; bp++) {
                float2 hv;
                {
                    float ii = fsig(ai[bp].x), ff = fsig(af[bp].x);
                    float gg = ftanh_(ag[bp].x), oo = fsig(ao[bp].x);
                    float c = c_sh[(2 * bp) * 608 + tid];
                    c = ff * c + ii * gg;
                    c_sh[(2 * bp) * 608 + tid] = c;
                    hv.x = oo * ftanh_(c);
                }
                {
                    float ii = fsig(ai[bp].y), ff = fsig(af[bp].y);
                    float gg = ftanh_(ag[bp].y), oo = fsig(ao[bp].y);
                    float c = c_sh[(2 * bp + 1) * 608 + tid];
                    c = ff * c + ii * gg;
                    c_sh[(2 * bp + 1) * 608 + tid] = c;
                    hv.y = oo * ftanh_(c);
                }
                h_sh[tid * HS + bp] = hv;
            }
        }
        __syncthreads();   // h_t visible

        // hsum = h[d=0] + h[d=1] -> g_hs[b][t][u]
        for (int i = tid; i < NB * 300; i += BT) {
            int b = i / 300, uu = i - b * 300;
            float2 h0 = h_sh[uu * HS + (b >> 1)];
            float2 h1 = h_sh[(300 + uu) * HS + (b >> 1)];
            float s = (b & 1) ? (h0.y + h1.y) : (h0.x + h1.x);
            g_hs[((size_t)(b0 + b) * TT + t) * 300 + uu] = s;
        }
    }
    __syncthreads();

    // ---------------- attention epilogue ----------------
    for (int i = tid; i < 300; i += BT) cw_sh[i] = conv_w[i];
    for (int i = tid; i < 300 * NCLS; i += BT) {
        int uu = i / NCLS, cls = i - uu * NCLS;
        fcT[i] = fc_w[(size_t)cls * 300 + uu];
    }
    __syncthreads();

    // Phase A: e[b][t] = sum_u tanh(hs[b][t][u]) * conv_w[u]
    {
        int wid = tid >> 5, lane = tid & 31;
        for (int task = wid; task < NB * TT; task += (BT / 32)) {
            int b = task / TT, t = task - b * TT;
            const float* hp = g_hs + ((size_t)(b0 + b) * TT + t) * 300;
            float s = 0.f;
            for (int uu = lane; uu < 300; uu += 32) s += ftanh_(hp[uu]) * cw_sh[uu];
            #pragma unroll
            for (int o = 16; o > 0; o >>= 1) s += __shfl_xor_sync(0xffffffffu, s, o);
            if (lane == 0) e_sh[b * 44 + t] = s;
        }
    }
    __syncthreads();

    if (tid < NB) {
        float m = -1e30f;
        for (int t = 0; t < TT; t++) m = fmaxf(m, e_sh[tid * 44 + t]);
        float ss = 0.f;
        for (int t = 0; t < TT; t++) { float p = __expf(e_sh[tid * 44 + t] - m); e_sh[tid * 44 + t] = p; ss += p; }
        float inv = 1.0f / ss;
        for (int t = 0; t < TT; t++) e_sh[tid * 44 + t] *= inv;
    }
    __syncthreads();

    // Phase B: r[b][u] = sum_t hs[b][t][u] * alpha[b][t]; hstar = tanh(r)
    for (int i = tid; i < NB * 300; i += BT) {
        int b = i / 300, uu = i - b * 300;
        const float* hp = g_hs + (size_t)(b0 + b) * TT * 300 + uu;
        float acc = 0.f;
        for (int t = 0; t < TT; t++) acc += hp[(size_t)t * 300] * e_sh[b * 44 + t];
        hstar[i] = ftanh_(acc);
    }
    __syncthreads();

    // FC + class softmax
    for (int b = 0; b < NB; b++) {
        if (tid < NCLS) {
            float acc = fc_b[tid];
            const float* hv = hstar + b * 300;
            for (int uu = 0; uu < 300; uu++) acc += hv[uu] * fcT[uu * NCLS + tid];
            l_sh[tid] = acc;
        }
        __syncthreads();
        if (tid < NCLS) {
            float m = -1e30f;
            for (int j = 0; j < NCLS; j++) m = fmaxf(m, l_sh[j]);
            p_sh[tid] = __expf(l_sh[tid] - m);
        }
        __syncthreads();
        if (tid < NCLS) {
            float s = 0.f;
            for (int j = 0; j < NCLS; j++) s += p_sh[j];
            out[(size_t)(b0 + b) * NCLS + tid] = p_sh[tid] / s;
        }
        __syncthreads();
    }
}

// ---------------- launch ------------------------------------------------------
extern "C" void kernel_launch(void* const* d_in, const int* in_sizes, int n_in,
                              void* d_out, int out_size) {
    const float* x      = (const float*)d_in[0];
    const float* w_ih   = (const float*)d_in[1];
    const float* w_hh   = (const float*)d_in[2];
    const float* b_ih   = (const float*)d_in[3];
    const float* b_hh   = (const float*)d_in[4];
    const float* conv_w = (const float*)d_in[5];
    const float* fc_w   = (const float*)d_in[6];
    const float* fc_b   = (const float*)d_in[7];
    float* out = (float*)d_out;

    cudaFuncSetAttribute(lstm_rec_kernel,
                         cudaFuncAttributeMaxDynamicSharedMemorySize, SMEM_BYTES);

    transpose_x_kernel<<<dim3(BSZ / 32, HDIM), 256>>>(x);
    prep_w_kernel<<<(2 * 600 * 300 * 4 + 255) / 256, 256>>>(w_ih, w_hh);
    prep_b_kernel<<<(2400 + 255) / 256, 256>>>(b_ih, b_hh);
    precompute_zx_kernel<<<dim3(BSZ / NB, TT), BT>>>();
    lstm_rec_kernel<<<BSZ / NB, BT, SMEM_BYTES>>>(conv_w, fc_w, fc_b, out);
}

// round 5
// speedup vs baseline: 2.3368x; 1.2631x over previous
#include <cuda_runtime.h>
#include <cuda_bf16.h>
#include <math.h>
#include <stdint.h>

// Problem constants
#define BSZ   4096
#define HDIM  300
#define TT    43
#define NCLS  80
#define NB    16     // batch rows per CTA (recurrent)
#define NBP   8      // float2 batch pairs
#define BT    608    // threads per block (19 warps; 600 active owners)
#define HS    10     // h_sh row stride in float2

// GEMM shapes
#define MROWS 2432          // 2*1200 padded to 19*128
#define KDIM  320           // 300 padded to 5*64
#define NCOLS 176128        // 43*4096
#define GMT   128
#define GNT   128
#define GKC   64
#define MTILES 19           // 2432/128
#define NTILES 1376         // 176128/128

// ---------------- device scratch ----------------------------------------------
__device__ float         g_hs[(size_t)BSZ * TT * HDIM];      // [b][t][h]
__device__ float4        g_W4[2 * 600 * 300 + 600];          // recurrent weights (gate-interleaved)
__device__ __nv_bfloat16 g_Wh[(size_t)MROWS * KDIM];         // W_ih hi  [row][k]
__device__ __nv_bfloat16 g_Wl[(size_t)MROWS * KDIM];         // W_ih lo
__device__ __nv_bfloat16 g_Xh[(size_t)NCOLS * KDIM];         // X hi  [col=(t*4096+b)][k]
__device__ __nv_bfloat16 g_Xl[(size_t)NCOLS * KDIM];         // X lo
__device__ float         g_zx2[(size_t)NCOLS * MROWS];       // [col][row]  z_x + bias
__device__ float         g_bias2432[MROWS];

// ---------------- math helpers -------------------------------------------------
__device__ __forceinline__ float2 ffma2(float2 a, float2 b, float2 c) {
    unsigned long long au = *reinterpret_cast<unsigned long long*>(&a);
    unsigned long long bu = *reinterpret_cast<unsigned long long*>(&b);
    unsigned long long cu = *reinterpret_cast<unsigned long long*>(&c);
    unsigned long long du;
    asm("fma.rn.f32x2 %0, %1, %2, %3;" : "=l"(du) : "l"(au), "l"(bu), "l"(cu));
    return *reinterpret_cast<float2*>(&du);
}
__device__ __forceinline__ float fsig(float x) {
    return __fdividef(1.0f, 1.0f + __expf(-x));
}
__device__ __forceinline__ float ftanh_(float x) {
    float e = __expf(2.0f * x);
    return 1.0f - __fdividef(2.0f, e + 1.0f);
}
__device__ __forceinline__ uint32_t smem_u32(const void* p) {
    uint32_t a;
    asm("{ .reg .u64 t; cvta.to.shared.u64 t, %1; cvt.u32.u64 %0, t; }" : "=r"(a) : "l"(p));
    return a;
}

// mma.sync m16n8k16 bf16 (row.col), D += A*B
__device__ __forceinline__ void mma16816(float* c, const uint32_t* a, const uint32_t* b) {
    asm volatile(
        "mma.sync.aligned.m16n8k16.row.col.f32.bf16.bf16.f32 "
        "{%0,%1,%2,%3}, {%4,%5,%6,%7}, {%8,%9}, {%0,%1,%2,%3};"
        : "+f"(c[0]), "+f"(c[1]), "+f"(c[2]), "+f"(c[3])
        : "r"(a[0]), "r"(a[1]), "r"(a[2]), "r"(a[3]), "r"(b[0]), "r"(b[1]));
}
#define LDSM4(r0, r1, r2, r3, addr)                                               \
    asm volatile("ldmatrix.sync.aligned.m8n8.x4.shared.b16 {%0,%1,%2,%3}, [%4];"  \
                 : "=r"(r0), "=r"(r1), "=r"(r2), "=r"(r3) : "r"(addr))

// ---------------- prep kernels -------------------------------------------------
// recurrent weights: g_W4[(d*600+k)*300+u] = (i,f,g,o)
__global__ void prep_w_kernel(const float* __restrict__ wih, const float* __restrict__ whh) {
    int idx = blockIdx.x * blockDim.x + threadIdx.x;
    if (idx >= 2 * 600 * 300 * 4) return;
    int gate = idx & 3;
    int rest = idx >> 2;
    int u = rest % 300;
    int k = (rest / 300) % 600;
    int d = rest / (300 * 600);
    int col = gate * 300 + u;
    float v;
    if (k < 300) v = wih[((size_t)d * 1200 + col) * 300 + k];
    else         v = whh[((size_t)d * 1200 + col) * 300 + (k - 300)];
    ((float*)g_W4)[idx] = v;
}

// bf16 split of W_ih rows (row = d*1200 + gate*300 + u), zero-padded
__global__ void prep_wsplit_kernel(const float* __restrict__ wih) {
    int idx = blockIdx.x * blockDim.x + threadIdx.x;
    if (idx >= MROWS * KDIM) return;
    int row = idx / KDIM, k = idx % KDIM;
    float v = 0.f;
    if (row < 2400 && k < 300) {
        int d = row / 1200, col = row % 1200;
        v = wih[((size_t)d * 1200 + col) * 300 + k];
    }
    __nv_bfloat16 hi = __float2bfloat16(v);
    __nv_bfloat16 lo = __float2bfloat16(v - __bfloat162float(hi));
    g_Wh[idx] = hi;
    g_Wl[idx] = lo;
}

// bf16 split of X: col n = t*4096+b; value x[b][k][t]
__global__ void prep_xsplit_kernel(const float* __restrict__ x) {
    size_t idx = (size_t)blockIdx.x * blockDim.x + threadIdx.x;
    if (idx >= (size_t)NCOLS * KDIM) return;
    size_t n = idx / KDIM;
    int k = (int)(idx % KDIM);
    int t = (int)(n >> 12);
    int b = (int)(n & 4095);
    float v = (k < 300) ? x[((size_t)b * 300 + k) * TT + t] : 0.f;
    __nv_bfloat16 hi = __float2bfloat16(v);
    __nv_bfloat16 lo = __float2bfloat16(v - __bfloat162float(hi));
    g_Xh[idx] = hi;
    g_Xl[idx] = lo;
}

__global__ void prep_bias_kernel(const float* __restrict__ bih, const float* __restrict__ bhh) {
    int row = blockIdx.x * blockDim.x + threadIdx.x;
    if (row >= MROWS) return;
    float v = 0.f;
    if (row < 2400) {
        int d = row / 1200, col = row % 1200;
        v = bih[(size_t)d * 1200 + col] + bhh[(size_t)d * 1200 + col];
    }
    g_bias2432[row] = v;
}

// ---------------- mma.sync GEMM: g_zx2[n][m] = sum_k W[m][k] X[n][k] + bias[m] -
// SMEM tiles, unswizzled, row stride 72 halves (144 B):
//   Ah @0, Al @18432, Bh @36864, Bl @55296  (18432 B each) -> 73728 B
#define GS_BYTES 73728
#define TROWB 144     // bytes per tile row

__global__ __launch_bounds__(256, 2)
void gemm_zx_kernel() {
    extern __shared__ char sm[];
    char* Ah = sm;
    char* Al = sm + 18432;
    char* Bh = sm + 36864;
    char* Bl = sm + 55296;
    const int tid  = threadIdx.x;
    const int lane = tid & 31;
    const int wid  = tid >> 5;
    const int wm   = wid & 1;        // 0..1 -> 64-row m group
    const int wn   = wid >> 1;       // 0..3 -> 32-col n group
    const int m0   = blockIdx.x * GMT;
    const int n0   = blockIdx.y * GNT;

    // per-lane ldmatrix address components (matrix id = lane>>3)
    // A x4: matrices (m0-7,k0),(m8-15,k0),(m0-7,k8),(m8-15,k8)
    const uint32_t aRowByte =
        (uint32_t)(wm * 64 + ((lane >> 3) & 1) * 8 + (lane & 7)) * TROWB + (lane >> 4) * 16;
    // B x4: matrices (n0-7,k0),(n0-7,k8),(n8-15,k0),(n8-15,k8)
    const uint32_t bRowByte =
        (uint32_t)(wn * 32 + (lane >> 4) * 8 + (lane & 7)) * TROWB + ((lane >> 3) & 1) * 16;

    const uint32_t baseAh = smem_u32(Ah), baseAl = smem_u32(Al);
    const uint32_t baseBh = smem_u32(Bh), baseBl = smem_u32(Bl);

    float acc[4][4][4];
    #pragma unroll
    for (int mt = 0; mt < 4; mt++)
        #pragma unroll
        for (int nt = 0; nt < 4; nt++)
            #pragma unroll
            for (int i = 0; i < 4; i++) acc[mt][nt][i] = 0.f;

    for (int chunk = 0; chunk < 5; chunk++) {
        const int kc0 = chunk * GKC;
        __syncthreads();
        // stage: 1024 16B-groups per tile; thread i handles rows r=i>>3, k-group c8=i&7
        for (int i = tid; i < 1024; i += 256) {
            int r = i >> 3, c8 = i & 7;
            uint32_t off = (uint32_t)r * TROWB + c8 * 16;
            size_t sa = (size_t)(m0 + r) * KDIM + kc0 + c8 * 8;
            size_t sb = (size_t)(n0 + r) * KDIM + kc0 + c8 * 8;
            *(uint4*)(Ah + off) = *(const uint4*)(g_Wh + sa);
            *(uint4*)(Al + off) = *(const uint4*)(g_Wl + sa);
            *(uint4*)(Bh + off) = *(const uint4*)(g_Xh + sb);
            *(uint4*)(Bl + off) = *(const uint4*)(g_Xl + sb);
        }
        __syncthreads();

        #pragma unroll
        for (int ks = 0; ks < 4; ks++) {
            const uint32_t kbb = ks * 32;   // 16 halves = 32 bytes
            uint32_t aF[4][4], bHF[4][2], bLF[4][2];
            #pragma unroll
            for (int mt = 0; mt < 4; mt++)
                LDSM4(aF[mt][0], aF[mt][1], aF[mt][2], aF[mt][3],
                      baseAh + aRowByte + mt * (16 * TROWB) + kbb);
            #pragma unroll
            for (int p = 0; p < 2; p++)
                LDSM4(bHF[2 * p][0], bHF[2 * p][1], bHF[2 * p + 1][0], bHF[2 * p + 1][1],
                      baseBh + bRowByte + p * (16 * TROWB) + kbb);
            #pragma unroll
            for (int p = 0; p < 2; p++)
                LDSM4(bLF[2 * p][0], bLF[2 * p][1], bLF[2 * p + 1][0], bLF[2 * p + 1][1],
                      baseBl + bRowByte + p * (16 * TROWB) + kbb);
            // hi*hi
            #pragma unroll
            for (int mt = 0; mt < 4; mt++)
                #pragma unroll
                for (int nt = 0; nt < 4; nt++)
                    mma16816(acc[mt][nt], aF[mt], bHF[nt]);
            // hi*lo
            #pragma unroll
            for (int mt = 0; mt < 4; mt++)
                #pragma unroll
                for (int nt = 0; nt < 4; nt++)
                    mma16816(acc[mt][nt], aF[mt], bLF[nt]);
            // lo*hi (reload A from Al over aF)
            #pragma unroll
            for (int mt = 0; mt < 4; mt++)
                LDSM4(aF[mt][0], aF[mt][1], aF[mt][2], aF[mt][3],
                      baseAl + aRowByte + mt * (16 * TROWB) + kbb);
            #pragma unroll
            for (int mt = 0; mt < 4; mt++)
                #pragma unroll
                for (int nt = 0; nt < 4; nt++)
                    mma16816(acc[mt][nt], aF[mt], bHF[nt]);
        }
    }

    // epilogue: add bias, store [n][m] (m runs fully within 32B sectors)
    const int rbase = m0 + wm * 64 + (lane >> 2);
    const int nbase = n0 + wn * 32 + (lane & 3) * 2;
    #pragma unroll
    for (int mt = 0; mt < 4; mt++) {
        int row = rbase + mt * 16;
        float br0 = g_bias2432[row];
        float br8 = g_bias2432[row + 8];
        #pragma unroll
        for (int nt = 0; nt < 4; nt++) {
            size_t n = (size_t)(nbase + nt * 8);
            g_zx2[n * MROWS + row]           = acc[mt][nt][0] + br0;
            g_zx2[(n + 1) * MROWS + row]     = acc[mt][nt][1] + br0;
            g_zx2[n * MROWS + row + 8]       = acc[mt][nt][2] + br8;
            g_zx2[(n + 1) * MROWS + row + 8] = acc[mt][nt][3] + br8;
        }
    }
}

// ---------------- FMA macro (recurrent) ----------------------------------------
#define GATE_FMAS(WA, V)                                                        \
    {                                                                           \
        float2 wp;                                                              \
        wp = make_float2((WA).x, (WA).x);                                       \
        _Pragma("unroll")                                                       \
        for (int bp = 0; bp < NBP; bp++) ai[bp] = ffma2((V)[bp], wp, ai[bp]);   \
        wp = make_float2((WA).y, (WA).y);                                       \
        _Pragma("unroll")                                                       \
        for (int bp = 0; bp < NBP; bp++) af[bp] = ffma2((V)[bp], wp, af[bp]);   \
        wp = make_float2((WA).z, (WA).z);                                       \
        _Pragma("unroll")                                                       \
        for (int bp = 0; bp < NBP; bp++) ag[bp] = ffma2((V)[bp], wp, ag[bp]);   \
        wp = make_float2((WA).w, (WA).w);                                       \
        _Pragma("unroll")                                                       \
        for (int bp = 0; bp < NBP; bp++) ao[bp] = ffma2((V)[bp], wp, ao[bp]);   \
    }

// ---------------- recurrent kernel + attention epilogue ------------------------
#define SMEM_BYTES 120000

__global__ __launch_bounds__(BT, 1)
void lstm_rec_kernel(const float* __restrict__ conv_w,
                     const float* __restrict__ fc_w,
                     const float* __restrict__ fc_b,
                     float* __restrict__ out) {
    extern __shared__ char smem_raw[];
    float2* h_sh  = (float2*)(smem_raw);
    float*  c_sh  = (float*) (smem_raw + 48000);
    float*  hstar = (float*) (smem_raw);
    float*  fcT   = (float*) (smem_raw + 19200);
    float*  aux   = (float*) (smem_raw + 115200);
    float*  cw_sh = aux;
    float*  e_sh  = aux + 300;
    float*  l_sh  = aux + 300 + 16 * 44;
    float*  p_sh  = l_sh + 80;

    const int tid = threadIdx.x;
    const int b0  = blockIdx.x * NB;

    for (int i = tid; i < 600 * HS; i += BT) h_sh[i] = make_float2(0.f, 0.f);
    for (int i = tid; i < 16 * 608; i += BT) c_sh[i] = 0.f;

    const bool active = (tid < 600);
    const int d = active ? (tid / 300) : 0;
    const int u = active ? (tid - d * 300) : 0;
    const float4* Wk = g_W4 + ((size_t)d * 600 + 300) * 300 + u;  // W_hh slice
    __syncthreads();

    for (int t = 0; t < TT; t++) {
        float2 ai[NBP], af[NBP], ag[NBP], ao[NBP];
        if (active) {
            // init accumulators from GEMM output (x-part + bias), layout [col][row]
            const float* zp = g_zx2 + ((size_t)t * 4096 + b0) * MROWS + (size_t)d * 1200 + u;
            #pragma unroll
            for (int bp = 0; bp < NBP; bp++) {
                ai[bp].x = zp[(size_t)(2 * bp) * MROWS + 0];
                ai[bp].y = zp[(size_t)(2 * bp + 1) * MROWS + 0];
                af[bp].x = zp[(size_t)(2 * bp) * MROWS + 300];
                af[bp].y = zp[(size_t)(2 * bp + 1) * MROWS + 300];
                ag[bp].x = zp[(size_t)(2 * bp) * MROWS + 600];
                ag[bp].y = zp[(size_t)(2 * bp + 1) * MROWS + 600];
                ao[bp].x = zp[(size_t)(2 * bp) * MROWS + 900];
                ao[bp].y = zp[(size_t)(2 * bp + 1) * MROWS + 900];
            }
            // recurrent GEMM: z += h_{t-1} @ W_hh^T
            const float2* hb = h_sh + (size_t)d * 300 * HS;
            float4 w0 = Wk[0];
            float4 w1 = Wk[300];
            for (int k = 0; k < 300; k++) {
                float4 wa = w0;
                w0 = w1;
                w1 = Wk[(size_t)(k + 2) * 300];   // tail reads hit pad region: valid, unused
                const float4* vp = (const float4*)(hb + (size_t)k * HS);
                float4 p0 = vp[0], p1 = vp[1], p2 = vp[2], p3 = vp[3];
                float2 v[NBP] = { make_float2(p0.x, p0.y), make_float2(p0.z, p0.w),
                                  make_float2(p1.x, p1.y), make_float2(p1.z, p1.w),
                                  make_float2(p2.x, p2.y), make_float2(p2.z, p2.w),
                                  make_float2(p3.x, p3.y), make_float2(p3.z, p3.w) };
                GATE_FMAS(wa, v);
            }
        }
        __syncthreads();

        if (active) {
            #pragma unroll
            for (int bp = 0; bp < NBP; bp++) {
                float2 hv;
                {
                    float ii = fsig(ai[bp].x), ff = fsig(af[bp].x);
                    float gg = ftanh_(ag[bp].x), oo = fsig(ao[bp].x);
                    float c = c_sh[(2 * bp) * 608 + tid];
                    c = ff * c + ii * gg;
                    c_sh[(2 * bp) * 608 + tid] = c;
                    hv.x = oo * ftanh_(c);
                }
                {
                    float ii = fsig(ai[bp].y), ff = fsig(af[bp].y);
                    float gg = ftanh_(ag[bp].y), oo = fsig(ao[bp].y);
                    float c = c_sh[(2 * bp + 1) * 608 + tid];
                    c = ff * c + ii * gg;
                    c_sh[(2 * bp + 1) * 608 + tid] = c;
                    hv.y = oo * ftanh_(c);
                }
                h_sh[tid * HS + bp] = hv;
            }
        }
        __syncthreads();

        for (int i = tid; i < NB * 300; i += BT) {
            int b = i / 300, uu = i - b * 300;
            float2 h0 = h_sh[uu * HS + (b >> 1)];
            float2 h1 = h_sh[(300 + uu) * HS + (b >> 1)];
            float s = (b & 1) ? (h0.y + h1.y) : (h0.x + h1.x);
            g_hs[((size_t)(b0 + b) * TT + t) * 300 + uu] = s;
        }
    }
    __syncthreads();

    // ---------------- attention epilogue ----------------
    for (int i = tid; i < 300; i += BT) cw_sh[i] = conv_w[i];
    for (int i = tid; i < 300 * NCLS; i += BT) {
        int uu = i / NCLS, cls = i - uu * NCLS;
        fcT[i] = fc_w[(size_t)cls * 300 + uu];
    }
    __syncthreads();

    {
        int wid = tid >> 5, lane = tid & 31;
        for (int task = wid; task < NB * TT; task += (BT / 32)) {
            int b = task / TT, t = task - b * TT;
            const float* hp = g_hs + ((size_t)(b0 + b) * TT + t) * 300;
            float s = 0.f;
            for (int uu = lane; uu < 300; uu += 32) s += ftanh_(hp[uu]) * cw_sh[uu];
            #pragma unroll
            for (int o = 16; o > 0; o >>= 1) s += __shfl_xor_sync(0xffffffffu, s, o);
            if (lane == 0) e_sh[b * 44 + t] = s;
        }
    }
    __syncthreads();

    if (tid < NB) {
        float m = -1e30f;
        for (int t = 0; t < TT; t++) m = fmaxf(m, e_sh[tid * 44 + t]);
        float ss = 0.f;
        for (int t = 0; t < TT; t++) { float p = __expf(e_sh[tid * 44 + t] - m); e_sh[tid * 44 + t] = p; ss += p; }
        float inv = 1.0f / ss;
        for (int t = 0; t < TT; t++) e_sh[tid * 44 + t] *= inv;
    }
    __syncthreads();

    for (int i = tid; i < NB * 300; i += BT) {
        int b = i / 300, uu = i - b * 300;
        const float* hp = g_hs + (size_t)(b0 + b) * TT * 300 + uu;
        float acc = 0.f;
        for (int t = 0; t < TT; t++) acc += hp[(size_t)t * 300] * e_sh[b * 44 + t];
        hstar[i] = ftanh_(acc);
    }
    __syncthreads();

    for (int b = 0; b < NB; b++) {
        if (tid < NCLS) {
            float acc = fc_b[tid];
            const float* hv = hstar + b * 300;
            for (int uu = 0; uu < 300; uu++) acc += hv[uu] * fcT[uu * NCLS + tid];
            l_sh[tid] = acc;
        }
        __syncthreads();
        if (tid < NCLS) {
            float m = -1e30f;
            for (int j = 0; j < NCLS; j++) m = fmaxf(m, l_sh[j]);
            p_sh[tid] = __expf(l_sh[tid] - m);
        }
        __syncthreads();
        if (tid < NCLS) {
            float s = 0.f;
            for (int j = 0; j < NCLS; j++) s += p_sh[j];
            out[(size_t)(b0 + b) * NCLS + tid] = p_sh[tid] / s;
        }
        __syncthreads();
    }
}

// ---------------- launch --------------------------------------------------------
extern "C" void kernel_launch(void* const* d_in, const int* in_sizes, int n_in,
                              void* d_out, int out_size) {
    const float* x      = (const float*)d_in[0];
    const float* w_ih   = (const float*)d_in[1];
    const float* w_hh   = (const float*)d_in[2];
    const float* b_ih   = (const float*)d_in[3];
    const float* b_hh   = (const float*)d_in[4];
    const float* conv_w = (const float*)d_in[5];
    const float* fc_w   = (const float*)d_in[6];
    const float* fc_b   = (const float*)d_in[7];
    float* out = (float*)d_out;

    cudaFuncSetAttribute(lstm_rec_kernel,
                         cudaFuncAttributeMaxDynamicSharedMemorySize, SMEM_BYTES);
    cudaFuncSetAttribute(gemm_zx_kernel,
                         cudaFuncAttributeMaxDynamicSharedMemorySize, GS_BYTES);

    prep_w_kernel<<<(2 * 600 * 300 * 4 + 255) / 256, 256>>>(w_ih, w_hh);
    prep_wsplit_kernel<<<(MROWS * KDIM + 255) / 256, 256>>>(w_ih);
    prep_xsplit_kernel<<<(int)(((size_t)NCOLS * KDIM + 255) / 256), 256>>>(x);
    prep_bias_kernel<<<(MROWS + 255) / 256, 256>>>(b_ih, b_hh);
    gemm_zx_kernel<<<dim3(MTILES, NTILES), 256, GS_BYTES>>>();
    lstm_rec_kernel<<<BSZ / NB, BT, SMEM_BYTES>>>(conv_w, fc_w, fc_b, out);
}